// round 10
// baseline (speedup 1.0000x reference)
#include <cuda_runtime.h>

#define BB    4
#define NN    8192
#define ALPHA 5.0f
#define EPS   1e-12f

#define SPLIT  16                // ref-dimension split
#define SLICE  (NN / SPLIT)      // 512 refs per block
#define SLICEP (SLICE / 2)       // 256 ref pairs (8 KB smem)
#define QB     128               // threads per knn block
#define QPT    2                 // queries per thread
#define QBLK   (QB * QPT)        // 256 queries per block
#define GX     (NN / QBLK)       // 32 query-groups per batch

#define FB     8                 // finish blocks per batch (8*1024 = NN)

typedef unsigned long long ull;
typedef unsigned int uint;

// Reversed-order float keys: min over floats == max over keys; 0 = identity.
__device__ uint  g_key [BB * NN];   // zero at load; k_finish self-resets
__device__ float g_dsum[BB * NN];
__device__ float g_bsum[BB];        // zeroed by k_knn each launch
__device__ int   g_done[BB];        // zero at load; self-resetting

__device__ __forceinline__ uint rkey(float f) {
    uint b = __float_as_uint(f);
    uint u = (b & 0x80000000u) ? ~b : (b | 0x80000000u);  // ascending order
    return ~u;                                            // descending
}
__device__ __forceinline__ float unrkey(uint r) {
    uint u = ~r;
    uint b = (u & 0x80000000u) ? (u & 0x7FFFFFFFu) : ~u;
    return __uint_as_float(b);
}

__device__ __forceinline__ ull f2u(float a, float b) {
    union { float f[2]; ull u; } t; t.f[0] = a; t.f[1] = b; return t.u;
}
__device__ __forceinline__ void u2f(ull v, float& a, float& b) {
    union { float f[2]; ull u; } t; t.u = v; a = t.f[0]; b = t.f[1];
}
__device__ __forceinline__ ull fma2(ull a, ull b, ull c) {
    ull d; asm("fma.rn.f32x2 %0, %1, %2, %3;" : "=l"(d) : "l"(a), "l"(b), "l"(c)); return d;
}

// Each block: 256 queries (2/thread) vs a 512-ref slice packed into smem.
// One-wave config: 14 blocks/SM x 148 SMs >= 2048 blocks.
// Window = 1 ref pair (small live range -> fits 36-reg cap without spills).
__global__ void __launch_bounds__(QB, 14) k_knn(const float* __restrict__ xyz,
                                                float* __restrict__ out) {
    __shared__ float4 sA[SLICEP];   // {x0,x1,y0,y1} per ref pair
    __shared__ float4 sB[SLICEP];   // {z0,z1,w0,w1}

    const int b     = blockIdx.y;
    const int slice = blockIdx.z;
    const int tid   = threadIdx.x;

    // per-replay resets (ordered before k_finish by the kernel boundary)
    if (blockIdx.x == 0 && slice == 0 && tid == 0) {
        if (b == 0) out[0] = 0.0f;
        g_bsum[b] = 0.0f;
    }

    // load + pack this block's ref slice (2 pairs per thread), float2 loads
    {
        const float2* __restrict__ src =
            (const float2*)(xyz + (size_t)(b * NN + slice * SLICE) * 3);
        #pragma unroll
        for (int k = 0; k < SLICEP / QB; k++) {
            int q = tid + k * QB;
            float2 f0 = src[3*q+0], f1 = src[3*q+1], f2 = src[3*q+2];
            float x0 = f0.x, y0 = f0.y, z0 = f1.x;
            float x1 = f1.y, y1 = f2.x, z1 = f2.y;
            float w0 = (x0*x0 + y0*y0) + z0*z0;
            float w1 = (x1*x1 + y1*y1) + z1*z1;
            sA[q] = make_float4(x0, x1, y0, y1);
            sB[q] = make_float4(z0, z1, w0, w1);
        }
    }

    const int qbase = blockIdx.x * QBLK + tid;
    ull mx[QPT], my[QPT], mz[QPT];
    #pragma unroll
    for (int k = 0; k < QPT; k++) {
        const float* qp = xyz + (size_t)(b * NN + qbase + k * QB) * 3;
        float qx = qp[0], qy = qp[1], qz = qp[2];
        mx[k] = f2u(-2.0f*qx, -2.0f*qx);
        my[k] = f2u(-2.0f*qy, -2.0f*qy);
        mz[k] = f2u(-2.0f*qz, -2.0f*qz);
    }

    __syncthreads();

    const bool self_block = (slice == (blockIdx.x >> 1));  // QBLK*2 == SLICE
    float part[QPT];

    if (!self_block) {
        // fast path: plain min, 2 accumulators per query
        float a0[QPT], a1[QPT];
        #pragma unroll
        for (int k = 0; k < QPT; k++) { a0[k] = 3.4e38f; a1[k] = 3.4e38f; }

        #pragma unroll 4
        for (int j = 0; j < SLICEP; j++) {
            float4 A = sA[j], B = sB[j];
            ull x = f2u(A.x, A.y), y = f2u(A.z, A.w);
            ull z = f2u(B.x, B.y), w = f2u(B.z, B.w);
            #pragma unroll
            for (int k = 0; k < QPT; k++) {
                ull t = fma2(mx[k], x, fma2(my[k], y, fma2(mz[k], z, w)));
                float c0, c1;
                u2f(t, c0, c1);
                a0[k] = fminf(a0[k], c0);
                a1[k] = fminf(a1[k], c1);
            }
        }
        #pragma unroll
        for (int k = 0; k < QPT; k++) part[k] = fminf(a0[k], a1[k]);
    } else {
        // self path: exact 2-min; emit second smallest (min excluding self)
        float s0[QPT], s1[QPT];
        #pragma unroll
        for (int k = 0; k < QPT; k++) { s0[k] = 3.4e38f; s1[k] = 3.4e38f; }

        #pragma unroll 2
        for (int j = 0; j < SLICEP; j++) {
            float4 A = sA[j], B = sB[j];
            ull x = f2u(A.x, A.y), y = f2u(A.z, A.w);
            ull z = f2u(B.x, B.y), w = f2u(B.z, B.w);
            #pragma unroll
            for (int k = 0; k < QPT; k++) {
                ull t = fma2(mx[k], x, fma2(my[k], y, fma2(mz[k], z, w)));
                float c0, c1;
                u2f(t, c0, c1);
                float v0 = fminf(c0, c1);
                float v1 = fmaxf(c0, c1);
                float hi = fmaxf(s0[k], v0);        // loser of the two mins
                s0[k] = fminf(s0[k], v0);
                s1[k] = fminf(fminf(s1[k], v1), hi);
            }
        }
        #pragma unroll
        for (int k = 0; k < QPT; k++) part[k] = s1[k];
    }

    #pragma unroll
    for (int k = 0; k < QPT; k++)
        atomicMax(&g_key[b * NN + qbase + k * QB], rkey(part[k]));
}

__device__ __forceinline__ float reduce1024(float v, float* sh) {
    int lane = threadIdx.x & 31, wid = threadIdx.x >> 5;
    #pragma unroll
    for (int o = 16; o; o >>= 1) v += __shfl_down_sync(0xFFFFFFFFu, v, o);
    if (lane == 0) sh[wid] = v;
    __syncthreads();
    if (wid == 0) {
        v = sh[lane];
        #pragma unroll
        for (int o = 16; o; o >>= 1) v += __shfl_down_sync(0xFFFFFFFFu, v, o);
    }
    return v;   // valid in thread 0
}

// grid (FB, BB) x 1024: decode key (+reset), dsum, batch sum. The last block
// per batch (fence+counter, self-resetting) computes the batch's masked loss.
__global__ void __launch_bounds__(1024) k_finish(const float* __restrict__ xyz,
                                                 float* __restrict__ out) {
    __shared__ float sh[32];
    __shared__ int lastflag;
    const int b = blockIdx.y;
    const int q = blockIdx.x * 1024 + threadIdx.x;
    const int i = b * NN + q;

    uint r = g_key[i];
    g_key[i] = 0;                                   // self-reset for replay
    float m = unrkey(r);

    const float* p = xyz + (size_t)i * 3;
    float px = p[0], py = p[1], pz = p[2];
    float w = (px*px + py*py) + pz*pz;
    float d2nn = w + m;                             // ||q||^2 + shifted min
    float mself = fmaf(-2.0f*px, px, fmaf(-2.0f*py, py, fmaf(-2.0f*pz, pz, w)));
    float d2self = w + mself;

    float ds = sqrtf(fmaxf(d2self, EPS)) + sqrtf(fmaxf(d2nn, EPS));
    g_dsum[i] = ds;

    float t = reduce1024(ds, sh);
    if (threadIdx.x == 0) {
        atomicAdd(&g_bsum[b], t);
        __threadfence();
        int d = atomicAdd(&g_done[b], 1);
        lastflag = (d == FB - 1);
        if (d == FB - 1) g_done[b] = 0;             // self-reset for replay
    }
    __syncthreads();
    if (!lastflag) return;
    __threadfence();   // acquire: all FB blocks' dsum/bsum writes visible

    float total = atomicAdd(&g_bsum[b], 0.0f);      // coherent read of batch sum
    float thr = (total / (float)NN) * ALPHA;        // mean, then *ALPHA (ref order)
    float s = 0.0f;
    #pragma unroll
    for (int k = 0; k < FB; k++) {
        float d = g_dsum[b * NN + k * 1024 + threadIdx.x];
        if (d > thr) s += d;
    }
    __syncthreads();                                // reuse sh[] safely
    s = reduce1024(s, sh);
    if (threadIdx.x == 0) atomicAdd(out, s);
}

extern "C" void kernel_launch(void* const* d_in, const int* in_sizes, int n_in,
                              void* d_out, int out_size) {
    const float* xyz = (const float*)d_in[0];
    float* out = (float*)d_out;

    dim3 grid(GX, BB, SPLIT);            // 32 x 4 x 16 = 2048 blocks, one wave
    k_knn<<<grid, QB>>>(xyz, out);

    dim3 fgrid(FB, BB);                  // 32 wide finish blocks
    k_finish<<<fgrid, 1024>>>(xyz, out);
}

// round 11
// speedup vs baseline: 1.2626x; 1.2626x over previous
#include <cuda_runtime.h>

#define BB    4
#define NN    8192
#define ALPHA 5.0f
#define EPS   1e-12f

#define SPLIT  32                // ref-dimension split (finer tasks -> smaller tail)
#define SLICE  (NN / SPLIT)      // 256 refs per block
#define SLICEP (SLICE / 2)       // 128 ref pairs (4 KB smem)
#define QB     128               // threads per knn block
#define QPT    2                 // queries per thread
#define QBLK   (QB * QPT)        // 256 queries per block
#define GX     (NN / QBLK)       // 32 query-groups per batch

#define FB     8                 // finish blocks per batch (8*1024 = NN)

typedef unsigned long long ull;
typedef unsigned int uint;

// Reversed-order float keys: min over floats == max over keys; 0 = identity.
__device__ uint  g_key [BB * NN];   // zero at load; k_dsum self-resets
__device__ float g_dsum[BB * NN];
__device__ float g_bsum[BB];        // zeroed by k_knn each launch

__device__ __forceinline__ uint rkey(float f) {
    uint b = __float_as_uint(f);
    uint u = (b & 0x80000000u) ? ~b : (b | 0x80000000u);  // ascending order
    return ~u;                                            // descending
}
__device__ __forceinline__ float unrkey(uint r) {
    uint u = ~r;
    uint b = (u & 0x80000000u) ? (u & 0x7FFFFFFFu) : ~u;
    return __uint_as_float(b);
}

__device__ __forceinline__ ull f2u(float a, float b) {
    union { float f[2]; ull u; } t; t.f[0] = a; t.f[1] = b; return t.u;
}
__device__ __forceinline__ void u2f(ull v, float& a, float& b) {
    union { float f[2]; ull u; } t; t.u = v; a = t.f[0]; b = t.f[1];
}
__device__ __forceinline__ ull fma2(ull a, ull b, ull c) {
    ull d; asm("fma.rn.f32x2 %0, %1, %2, %3;" : "=l"(d) : "l"(a), "l"(b), "l"(c)); return d;
}

// Each block: 256 queries (2/thread) vs a 256-ref slice packed into smem.
// Emits per-query partial min of (w_j - 2*dot_j) via one atomicMax(rkey).
// The 1-in-32 self block runs exact 2-min and emits the second smallest.
__global__ void __launch_bounds__(QB, 12) k_knn(const float* __restrict__ xyz,
                                                float* __restrict__ out) {
    __shared__ float4 sA[SLICEP];   // {x0,x1,y0,y1} per ref pair
    __shared__ float4 sB[SLICEP];   // {z0,z1,w0,w1}

    const int b     = blockIdx.y;
    const int slice = blockIdx.z;
    const int tid   = threadIdx.x;

    // per-replay resets (ordered before k_dsum/k_loss by kernel boundaries)
    if (blockIdx.x == 0 && slice == 0 && tid == 0) {
        if (b == 0) out[0] = 0.0f;
        g_bsum[b] = 0.0f;
    }

    // load + pack this block's ref slice (1 pair per thread), float2 loads
    {
        const float2* __restrict__ src =
            (const float2*)(xyz + (size_t)(b * NN + slice * SLICE) * 3);
        int q = tid;   // SLICEP == QB
        float2 f0 = src[3*q+0], f1 = src[3*q+1], f2 = src[3*q+2];
        float x0 = f0.x, y0 = f0.y, z0 = f1.x;
        float x1 = f1.y, y1 = f2.x, z1 = f2.y;
        float w0 = (x0*x0 + y0*y0) + z0*z0;
        float w1 = (x1*x1 + y1*y1) + z1*z1;
        sA[q] = make_float4(x0, x1, y0, y1);
        sB[q] = make_float4(z0, z1, w0, w1);
    }

    const int qbase = blockIdx.x * QBLK + tid;
    ull mx[QPT], my[QPT], mz[QPT];
    #pragma unroll
    for (int k = 0; k < QPT; k++) {
        const float* qp = xyz + (size_t)(b * NN + qbase + k * QB) * 3;
        float qx = qp[0], qy = qp[1], qz = qp[2];
        mx[k] = f2u(-2.0f*qx, -2.0f*qx);
        my[k] = f2u(-2.0f*qy, -2.0f*qy);
        mz[k] = f2u(-2.0f*qz, -2.0f*qz);
    }

    __syncthreads();

    const bool self_block = (slice == blockIdx.x);   // QBLK == SLICE
    float part[QPT];

    if (!self_block) {
        // fast path: plain min, 2 accumulators per query
        float a0[QPT], a1[QPT];
        #pragma unroll
        for (int k = 0; k < QPT; k++) { a0[k] = 3.4e38f; a1[k] = 3.4e38f; }

        #pragma unroll 2
        for (int j = 0; j < SLICEP; j += 2) {
            float4 A0 = sA[j],   B0 = sB[j];
            float4 A1 = sA[j+1], B1 = sB[j+1];
            ull x0 = f2u(A0.x, A0.y), y0 = f2u(A0.z, A0.w);
            ull z0 = f2u(B0.x, B0.y), w0 = f2u(B0.z, B0.w);
            ull x1 = f2u(A1.x, A1.y), y1 = f2u(A1.z, A1.w);
            ull z1 = f2u(B1.x, B1.y), w1 = f2u(B1.z, B1.w);
            #pragma unroll
            for (int k = 0; k < QPT; k++) {
                ull t0 = fma2(mx[k], x0, fma2(my[k], y0, fma2(mz[k], z0, w0)));
                ull t1 = fma2(mx[k], x1, fma2(my[k], y1, fma2(mz[k], z1, w1)));
                float c0, c1, c2, c3;
                u2f(t0, c0, c1); u2f(t1, c2, c3);
                a0[k] = fminf(a0[k], fminf(c0, c2));
                a1[k] = fminf(a1[k], fminf(c1, c3));
            }
        }
        #pragma unroll
        for (int k = 0; k < QPT; k++) part[k] = fminf(a0[k], a1[k]);
    } else {
        // self path: exact 2-min; emit second smallest (min excluding self)
        float s0[QPT], s1[QPT];
        #pragma unroll
        for (int k = 0; k < QPT; k++) { s0[k] = 3.4e38f; s1[k] = 3.4e38f; }

        for (int j = 0; j < SLICEP; j += 2) {
            float4 A0 = sA[j],   B0 = sB[j];
            float4 A1 = sA[j+1], B1 = sB[j+1];
            ull x0 = f2u(A0.x, A0.y), y0 = f2u(A0.z, A0.w);
            ull z0 = f2u(B0.x, B0.y), w0 = f2u(B0.z, B0.w);
            ull x1 = f2u(A1.x, A1.y), y1 = f2u(A1.z, A1.w);
            ull z1 = f2u(B1.x, B1.y), w1 = f2u(B1.z, B1.w);
            #pragma unroll
            for (int k = 0; k < QPT; k++) {
                ull t0 = fma2(mx[k], x0, fma2(my[k], y0, fma2(mz[k], z0, w0)));
                ull t1 = fma2(mx[k], x1, fma2(my[k], y1, fma2(mz[k], z1, w1)));
                float c0, c1, c2, c3;
                u2f(t0, c0, c1); u2f(t1, c2, c3);
                float m1 = fminf(c0, c1), M1 = fmaxf(c0, c1);
                float m2 = fminf(c2, c3), M2 = fmaxf(c2, c3);
                float v0 = fminf(m1, m2);
                float v1 = fminf(fmaxf(m1, m2), fminf(M1, M2));
                float n0 = fminf(v0, s0[k]);
                float tt = fmaxf(v0, s0[k]);
                float uu = fminf(v1, s1[k]);
                s0[k] = n0; s1[k] = fminf(tt, uu);
            }
        }
        #pragma unroll
        for (int k = 0; k < QPT; k++) part[k] = s1[k];
    }

    #pragma unroll
    for (int k = 0; k < QPT; k++)
        atomicMax(&g_key[b * NN + qbase + k * QB], rkey(part[k]));
}

__device__ __forceinline__ float reduce1024(float v, float* sh) {
    int lane = threadIdx.x & 31, wid = threadIdx.x >> 5;
    #pragma unroll
    for (int o = 16; o; o >>= 1) v += __shfl_down_sync(0xFFFFFFFFu, v, o);
    if (lane == 0) sh[wid] = v;
    __syncthreads();
    if (wid == 0) {
        v = sh[lane];
        #pragma unroll
        for (int o = 16; o; o >>= 1) v += __shfl_down_sync(0xFFFFFFFFu, v, o);
    }
    return v;   // valid in thread 0
}

// grid (FB, BB) x 1024: one point/thread. Decode key (+reset), dsum, batch sum.
__global__ void __launch_bounds__(1024) k_dsum(const float* __restrict__ xyz) {
    __shared__ float sh[32];
    const int b = blockIdx.y;
    const int q = blockIdx.x * 1024 + threadIdx.x;
    const int i = b * NN + q;

    uint r = g_key[i];
    g_key[i] = 0;                                   // self-reset for replay
    float m = unrkey(r);

    const float* p = xyz + (size_t)i * 3;
    float px = p[0], py = p[1], pz = p[2];
    float w = (px*px + py*py) + pz*pz;
    float d2nn = w + m;                             // ||q||^2 + shifted min
    float mself = fmaf(-2.0f*px, px, fmaf(-2.0f*py, py, fmaf(-2.0f*pz, pz, w)));
    float d2self = w + mself;

    float ds = sqrtf(fmaxf(d2self, EPS)) + sqrtf(fmaxf(d2nn, EPS));
    g_dsum[i] = ds;

    float t = reduce1024(ds, sh);
    if (threadIdx.x == 0) atomicAdd(&g_bsum[b], t);
}

// grid (FB, BB) x 1024: threshold (bsum final at kernel boundary), masked sum.
__global__ void __launch_bounds__(1024) k_loss(float* __restrict__ out) {
    __shared__ float sh[32];
    const int b = blockIdx.y;
    const int i = b * NN + blockIdx.x * 1024 + threadIdx.x;

    float thr = (g_bsum[b] / (float)NN) * ALPHA;    // mean, then *ALPHA (ref order)
    float d = g_dsum[i];
    float s = (d > thr) ? d : 0.0f;
    s = reduce1024(s, sh);
    if (threadIdx.x == 0) atomicAdd(out, s);
}

extern "C" void kernel_launch(void* const* d_in, const int* in_sizes, int n_in,
                              void* d_out, int out_size) {
    const float* xyz = (const float*)d_in[0];
    float* out = (float*)d_out;

    dim3 grid(GX, BB, SPLIT);            // 32 x 4 x 32 = 4096 blocks
    k_knn<<<grid, QB>>>(xyz, out);

    dim3 fgrid(FB, BB);                  // 32 wide finish blocks
    k_dsum<<<fgrid, 1024>>>(xyz);
    k_loss<<<fgrid, 1024>>>(out);
}

// round 12
// speedup vs baseline: 1.2714x; 1.0070x over previous
#include <cuda_runtime.h>

#define BB    4
#define NN    8192
#define ALPHA 5.0f
#define EPS   1e-12f

#define SPLIT  64                // ref-dimension split
#define SLICE  (NN / SPLIT)      // 128 refs per block (2 KB smem)
#define QB     128               // threads per knn block
#define QPT    4                 // queries per thread (2 packed lanes x 2)
#define QBLK   (QB * QPT)        // 512 queries per block
#define GX     (NN / QBLK)       // 16 query-groups per batch

#define FB     8                 // finish blocks per batch (8*1024 = NN)

typedef unsigned long long ull;
typedef unsigned int uint;

// Reversed-order float keys: min over floats == max over keys; 0 = identity.
__device__ uint  g_key [BB * NN];   // zero at load; k_dsum self-resets
__device__ float g_dsum[BB * NN];
__device__ float g_bsum[BB];        // zeroed by k_knn each launch

__device__ __forceinline__ uint rkey(float f) {
    uint b = __float_as_uint(f);
    uint u = (b & 0x80000000u) ? ~b : (b | 0x80000000u);  // ascending order
    return ~u;                                            // descending
}
__device__ __forceinline__ float unrkey(uint r) {
    uint u = ~r;
    uint b = (u & 0x80000000u) ? (u & 0x7FFFFFFFu) : ~u;
    return __uint_as_float(b);
}

__device__ __forceinline__ ull f2u(float a, float b) {
    union { float f[2]; ull u; } t; t.f[0] = a; t.f[1] = b; return t.u;
}
__device__ __forceinline__ void u2f(ull v, float& a, float& b) {
    union { float f[2]; ull u; } t; t.u = v; a = t.f[0]; b = t.f[1];
}
__device__ __forceinline__ ull fma2(ull a, ull b, ull c) {
    ull d; asm("fma.rn.f32x2 %0, %1, %2, %3;" : "=l"(d) : "l"(a), "l"(b), "l"(c)); return d;
}

// Each block: 512 queries (4/thread, packed 2-per-f32x2-lane) vs a 128-ref
// slice in smem as plain float4 (x,y,z,w). One broadcast LDS.128 per ref
// serves all 4 queries. Emits per-query partial min of (w_j - 2*dot_j).
// In the self block (slice covers query-group k = slice&3), track 2-min and
// emit the second smallest for that group (self is its strict slice min).
__global__ void __launch_bounds__(QB, 10) k_knn(const float* __restrict__ xyz,
                                                float* __restrict__ out) {
    __shared__ float4 sR[SLICE];    // (x, y, z, ||r||^2) per ref

    const int b     = blockIdx.y;
    const int slice = blockIdx.z;
    const int tid   = threadIdx.x;

    // per-replay resets (ordered before k_dsum/k_loss by kernel boundaries)
    if (blockIdx.x == 0 && slice == 0 && tid == 0) {
        if (b == 0) out[0] = 0.0f;
        g_bsum[b] = 0.0f;
    }

    // load this block's ref slice (1 ref per thread; SLICE == QB)
    {
        const float* __restrict__ src = xyz + (size_t)(b * NN + slice * SLICE + tid) * 3;
        float x = src[0], y = src[1], z = src[2];
        float w = (x*x + y*y) + z*z;                 // match jnp.sum order
        sR[tid] = make_float4(x, y, z, w);
    }

    // 4 queries per thread at tid + k*QB; packed as (q0,q1) and (q2,q3)
    const int qbase = blockIdx.x * QBLK + tid;
    ull mx01, my01, mz01, mx23, my23, mz23;
    {
        const float* q0 = xyz + (size_t)(b * NN + qbase + 0 * QB) * 3;
        const float* q1 = xyz + (size_t)(b * NN + qbase + 1 * QB) * 3;
        const float* q2 = xyz + (size_t)(b * NN + qbase + 2 * QB) * 3;
        const float* q3 = xyz + (size_t)(b * NN + qbase + 3 * QB) * 3;
        mx01 = f2u(-2.0f*q0[0], -2.0f*q1[0]);
        my01 = f2u(-2.0f*q0[1], -2.0f*q1[1]);
        mz01 = f2u(-2.0f*q0[2], -2.0f*q1[2]);
        mx23 = f2u(-2.0f*q2[0], -2.0f*q3[0]);
        my23 = f2u(-2.0f*q2[1], -2.0f*q3[1]);
        mz23 = f2u(-2.0f*q2[2], -2.0f*q3[2]);
    }

    __syncthreads();

    const bool self_block = ((slice >> 2) == blockIdx.x);  // QBLK == 4*SLICE
    float part[QPT];

    if (!self_block) {
        // fast path: plain min, 1 accumulator per query (issue stream hides chain)
        float a0 = 3.4e38f, a1 = 3.4e38f, a2 = 3.4e38f, a3 = 3.4e38f;

        #pragma unroll 4
        for (int j = 0; j < SLICE; j++) {
            float4 R = sR[j];
            ull xx = f2u(R.x, R.x), yy = f2u(R.y, R.y);
            ull zz = f2u(R.z, R.z), ww = f2u(R.w, R.w);
            ull t01 = fma2(mx01, xx, fma2(my01, yy, fma2(mz01, zz, ww)));
            ull t23 = fma2(mx23, xx, fma2(my23, yy, fma2(mz23, zz, ww)));
            float c0, c1, c2, c3;
            u2f(t01, c0, c1); u2f(t23, c2, c3);
            a0 = fminf(a0, c0);
            a1 = fminf(a1, c1);
            a2 = fminf(a2, c2);
            a3 = fminf(a3, c3);
        }
        part[0] = a0; part[1] = a1; part[2] = a2; part[3] = a3;
    } else {
        // self path: 2-min per query; one query-group (slice&3) excludes self
        float s0[QPT], s1[QPT];
        #pragma unroll
        for (int k = 0; k < QPT; k++) { s0[k] = 3.4e38f; s1[k] = 3.4e38f; }

        #pragma unroll 2
        for (int j = 0; j < SLICE; j++) {
            float4 R = sR[j];
            ull xx = f2u(R.x, R.x), yy = f2u(R.y, R.y);
            ull zz = f2u(R.z, R.z), ww = f2u(R.w, R.w);
            ull t01 = fma2(mx01, xx, fma2(my01, yy, fma2(mz01, zz, ww)));
            ull t23 = fma2(mx23, xx, fma2(my23, yy, fma2(mz23, zz, ww)));
            float c[QPT];
            u2f(t01, c[0], c[1]); u2f(t23, c[2], c[3]);
            #pragma unroll
            for (int k = 0; k < QPT; k++) {
                float hi = fmaxf(s0[k], c[k]);
                s0[k] = fminf(s0[k], c[k]);
                s1[k] = fminf(s1[k], hi);
            }
        }
        const int special = slice & 3;               // group whose selves are here
        #pragma unroll
        for (int k = 0; k < QPT; k++)
            part[k] = (k == special) ? s1[k] : s0[k];
    }

    #pragma unroll
    for (int k = 0; k < QPT; k++)
        atomicMax(&g_key[b * NN + qbase + k * QB], rkey(part[k]));
}

__device__ __forceinline__ float reduce1024(float v, float* sh) {
    int lane = threadIdx.x & 31, wid = threadIdx.x >> 5;
    #pragma unroll
    for (int o = 16; o; o >>= 1) v += __shfl_down_sync(0xFFFFFFFFu, v, o);
    if (lane == 0) sh[wid] = v;
    __syncthreads();
    if (wid == 0) {
        v = sh[lane];
        #pragma unroll
        for (int o = 16; o; o >>= 1) v += __shfl_down_sync(0xFFFFFFFFu, v, o);
    }
    return v;   // valid in thread 0
}

// grid (FB, BB) x 1024: one point/thread. Decode key (+reset), dsum, batch sum.
__global__ void __launch_bounds__(1024) k_dsum(const float* __restrict__ xyz) {
    __shared__ float sh[32];
    const int b = blockIdx.y;
    const int q = blockIdx.x * 1024 + threadIdx.x;
    const int i = b * NN + q;

    uint r = g_key[i];
    g_key[i] = 0;                                   // self-reset for replay
    float m = unrkey(r);

    const float* p = xyz + (size_t)i * 3;
    float px = p[0], py = p[1], pz = p[2];
    float w = (px*px + py*py) + pz*pz;
    float d2nn = w + m;                             // ||q||^2 + shifted min
    float mself = fmaf(-2.0f*px, px, fmaf(-2.0f*py, py, fmaf(-2.0f*pz, pz, w)));
    float d2self = w + mself;

    float ds = sqrtf(fmaxf(d2self, EPS)) + sqrtf(fmaxf(d2nn, EPS));
    g_dsum[i] = ds;

    float t = reduce1024(ds, sh);
    if (threadIdx.x == 0) atomicAdd(&g_bsum[b], t);
}

// grid (FB, BB) x 1024: threshold (bsum final at kernel boundary), masked sum.
__global__ void __launch_bounds__(1024) k_loss(float* __restrict__ out) {
    __shared__ float sh[32];
    const int b = blockIdx.y;
    const int i = b * NN + blockIdx.x * 1024 + threadIdx.x;

    float thr = (g_bsum[b] / (float)NN) * ALPHA;    // mean, then *ALPHA (ref order)
    float d = g_dsum[i];
    float s = (d > thr) ? d : 0.0f;
    s = reduce1024(s, sh);
    if (threadIdx.x == 0) atomicAdd(out, s);
}

extern "C" void kernel_launch(void* const* d_in, const int* in_sizes, int n_in,
                              void* d_out, int out_size) {
    const float* xyz = (const float*)d_in[0];
    float* out = (float*)d_out;

    dim3 grid(GX, BB, SPLIT);            // 16 x 4 x 64 = 4096 blocks
    k_knn<<<grid, QB>>>(xyz, out);

    dim3 fgrid(FB, BB);                  // 32 wide finish blocks
    k_dsum<<<fgrid, 1024>>>(xyz);
    k_loss<<<fgrid, 1024>>>(out);
}